// round 9
// baseline (speedup 1.0000x reference)
#include <cuda_runtime.h>

#define D 2048
#define B 16

// Scratch (allocation-free rule: device globals)
__device__ float g_u[B * D];
__device__ float g_diag[B * D];

typedef unsigned long long u64;

// ---- packed f32x2 helpers (Blackwell sm_100+) ----
__device__ __forceinline__ u64 pk2(float lo, float hi) {
    u64 r;
    asm("mov.b64 %0, {%1, %2};" : "=l"(r) : "f"(lo), "f"(hi));
    return r;
}
__device__ __forceinline__ void unpk2(float& lo, float& hi, u64 v) {
    asm("mov.b64 {%0, %1}, %2;" : "=f"(lo), "=f"(hi) : "l"(v));
}
__device__ __forceinline__ void ffma2(u64& acc, u64 a, u64 b) {
    asm("fma.rn.f32x2 %0, %1, %2, %0;" : "+l"(acc) : "l"(a), "l"(b));
}

__device__ __forceinline__ float sigmoidf(float x) {
    return 1.0f / (1.0f + __expf(-x));
}

// Warp transpose-reduce: lane l ends with (in v[0]) the 32-lane total of
// logical index l.
__device__ __forceinline__ void treduce32(float (&v)[32], int lane) {
#pragma unroll
    for (int m = 16; m > 0; m >>= 1) {
#pragma unroll
        for (int t = 0; t < 16; t++) {
            if (t < m) {
                float lo = v[t];
                float hi = v[t + m];
                float send = (lane & m) ? lo : hi;
                float recv = __shfl_xor_sync(0xffffffffu, send, m);
                v[t] = (lane & m) ? (hi + recv) : (lo + recv);
            }
        }
    }
}

__device__ __forceinline__ void finalize_one(
    int b, int i, float dA, float dX,
    const float* __restrict__ xt, const float* __restrict__ h,
    const float* __restrict__ ba, const float* __restrict__ bx,
    const float* __restrict__ Lam)
{
    float rt = sigmoidf(dA + __ldg(ba + i));
    float it = sigmoidf(dX + __ldg(bx + i));
    float la = -log1pf(__expf(-__ldg(Lam + i)));   // -softplus(-Lam)
    float t  = la * rt * 0.125f;                   // /C, C=8
    float a  = __expf(t);
    float om = -expm1f(2.0f * t);                  // 1 - a^2, cancellation-free
    float u  = sqrtf(fmaxf(om, 0.0f)) * it * __ldg(xt + b * D + i);
    g_u[b * D + i]    = u;
    g_diag[b * D + i] = a * __ldg(h + b * D + i);
}

// Gates with intra-block K-split and packed f32x2 FMAs:
//   Block = 256 threads (8 warps), owns 8 columns [blockIdx.x*8, +8).
//   Warps 0-3: K in [0,1024); warps 4-7: K in [1024,2048).
//   Warp w: column pair (i0, i1) packed in f32x2 lo/hi halves,
//   BOTH matrices, ALL 16 batches. Grid: 256 blocks -> 2048 warps.
__global__ __launch_bounds__(256, 2) void gates_kernel(
    const float* __restrict__ xt, const float* __restrict__ h,
    const float* __restrict__ Wa, const float* __restrict__ Wx,
    const float* __restrict__ ba, const float* __restrict__ bx,
    const float* __restrict__ Lam)
{
    // Two staged xt regions (one per K-half): 2 x 16 x 64 float4 = 32 KB
    __shared__ float4 xs4[2 * B * 64];

    const int tid   = threadIdx.x;
    const int lane  = tid & 31;
    const int warp  = tid >> 5;
    const int kh    = warp >> 2;                 // K-half: 0 or 1
    const int i0    = blockIdx.x * 8 + (warp & 3) * 2;
    const int i1    = i0 + 1;

    // Packed accumulators: lo = col i0, hi = col i1.
    u64 accA[16], accX[16];
#pragma unroll
    for (int t = 0; t < 16; t++) { accA[t] = 0ull; accX[t] = 0ull; }

    const float4* xt4 = reinterpret_cast<const float4*>(xt);

#pragma unroll 1
    for (int kt = 0; kt < 1024; kt += 256) {
        __syncthreads();
        // Stage xt[b, r*1024 + kt .. +256) for r=0,1 (2048 float4, 8/thread)
#pragma unroll
        for (int e = tid; e < 2 * B * 64; e += 256) {
            int r   = e >> 10;           // region (K-half)
            int rem = e & 1023;
            int b   = rem >> 6;
            int c   = rem & 63;
            xs4[e] = xt4[b * (D / 4) + ((r * 1024 + kt) >> 2) + c];
        }
        __syncthreads();

        const int wbase = kh * 1024 + kt;   // this warp's K offset (floats)
        const float4* wa0p = reinterpret_cast<const float4*>(Wa + (size_t)i0 * D + wbase);
        const float4* wa1p = reinterpret_cast<const float4*>(Wa + (size_t)i1 * D + wbase);
        const float4* wx0p = reinterpret_cast<const float4*>(Wx + (size_t)i0 * D + wbase);
        const float4* wx1p = reinterpret_cast<const float4*>(Wx + (size_t)i1 * D + wbase);
        const float4* xbase = xs4 + kh * B * 64;

#pragma unroll
        for (int m = 0; m < 2; m++) {
            const int idx = m * 32 + lane;
            float4 wa0 = __ldg(wa0p + idx);
            float4 wa1 = __ldg(wa1p + idx);
            float4 wx0 = __ldg(wx0p + idx);
            float4 wx1 = __ldg(wx1p + idx);

            // Pack weight pairs (col i0 in lo, col i1 in hi)
            u64 wpa0 = pk2(wa0.x, wa1.x);
            u64 wpa1 = pk2(wa0.y, wa1.y);
            u64 wpa2 = pk2(wa0.z, wa1.z);
            u64 wpa3 = pk2(wa0.w, wa1.w);
            u64 wpx0 = pk2(wx0.x, wx1.x);
            u64 wpx1 = pk2(wx0.y, wx1.y);
            u64 wpx2 = pk2(wx0.z, wx1.z);
            u64 wpx3 = pk2(wx0.w, wx1.w);

#pragma unroll
            for (int b = 0; b < 16; b++) {
                float4 x = xbase[b * 64 + idx];
                u64 xx0 = pk2(x.x, x.x);
                u64 xx1 = pk2(x.y, x.y);
                u64 xx2 = pk2(x.z, x.z);
                u64 xx3 = pk2(x.w, x.w);

                ffma2(accA[b], wpa0, xx0);
                ffma2(accA[b], wpa1, xx1);
                ffma2(accA[b], wpa2, xx2);
                ffma2(accA[b], wpa3, xx3);

                ffma2(accX[b], wpx0, xx0);
                ffma2(accX[b], wpx1, xx1);
                ffma2(accX[b], wpx2, xx2);
                ffma2(accX[b], wpx3, xx3);
            }
        }
    }

    // Unpack into the logical layout expected by treduce32:
    // vA: col i0 -> [0..15]=dotA(b), [16..31]=dotX(b). vB: col i1.
    float vA[32], vB[32];
#pragma unroll
    for (int b = 0; b < 16; b++) {
        unpk2(vA[b],      vB[b],      accA[b]);
        unpk2(vA[16 + b], vB[16 + b], accX[b]);
    }

    treduce32(vA, lane);   // lane l: sum for col i0, mat = l>>4, b = l&15
    treduce32(vB, lane);
    float rA = vA[0], rB = vB[0];

    // Combine the two K-halves through smem (reuse xs4 storage).
    float* sred = reinterpret_cast<float*>(xs4);   // 4 warps x 64 floats
    __syncthreads();                               // everyone done with xs4
    if (kh == 0) {
        sred[(warp & 3) * 64 + lane]      = rA;
        sred[(warp & 3) * 64 + 32 + lane] = rB;
    }
    __syncthreads();
    if (kh == 1) {
        rA += sred[(warp & 3) * 64 + lane];
        rB += sred[(warp & 3) * 64 + 32 + lane];

        float pA = __shfl_xor_sync(0xffffffffu, rA, 16);  // pair dotA <-> dotX
        float pB = __shfl_xor_sync(0xffffffffu, rB, 16);

        if (lane < 16) {
            finalize_one(lane, i0, rA, pA, xt, h, ba, bx, Lam);
            finalize_one(lane, i1, rB, pB, xt, h, ba, bx, Lam);
        }
    }
}

// Writer: ht[b,i,j] = u[b,j] + (i==j)*diag[b,i].
// Block = (batch b, 16 consecutive rows i). u row held in registers
// (2 float4 / thread, 256 threads = 2048 floats). Streaming stores.
__global__ __launch_bounds__(256) void writer_kernel(float* __restrict__ out) {
    const int b   = blockIdx.y;
    const int i0  = blockIdx.x * 16;
    const int tid = threadIdx.x;

    const float4* u4 = reinterpret_cast<const float4*>(g_u + b * D);
    const float4  va = __ldg(u4 + tid);
    const float4  vb = __ldg(u4 + tid + 256);
    const float*  dg = g_diag + b * D;

    float* obase = out + ((size_t)b * D + (size_t)i0) * D;

#pragma unroll 4
    for (int r = 0; r < 16; r++) {
        const int i  = i0 + r;
        const float dv = __ldg(dg + i);
        float4 sa = va, sb = vb;
        const int q = i >> 2, c = i & 3;
        if (q == tid) {
            if      (c == 0) sa.x += dv;
            else if (c == 1) sa.y += dv;
            else if (c == 2) sa.z += dv;
            else             sa.w += dv;
        } else if (q - 256 == tid) {
            if      (c == 0) sb.x += dv;
            else if (c == 1) sb.y += dv;
            else if (c == 2) sb.z += dv;
            else             sb.w += dv;
        }
        float4* orow = reinterpret_cast<float4*>(obase + (size_t)r * D);
        __stcs(orow + tid, sa);
        __stcs(orow + tid + 256, sb);
    }
}

extern "C" void kernel_launch(void* const* d_in, const int* in_sizes, int n_in,
                              void* d_out, int out_size) {
    const float* xt  = (const float*)d_in[0];
    const float* h   = (const float*)d_in[1];
    const float* Wa  = (const float*)d_in[2];
    const float* Wx  = (const float*)d_in[3];
    const float* ba  = (const float*)d_in[4];
    const float* bx  = (const float*)d_in[5];
    const float* Lam = (const float*)d_in[6];

    gates_kernel<<<256, 256>>>(xt, h, Wa, Wx, ba, bx, Lam);

    dim3 grid(D / 16, B);
    writer_kernel<<<grid, 256>>>((float*)d_out);
}